// round 15
// baseline (speedup 1.0000x reference)
#include <cuda_runtime.h>
#include <cstdint>

// PoolingNms: MaxPool2d(k=3, stride=3) + MaxUnpool2d fused.
// x: [16, 1, 1536, 1536] fp32. Keep per-3x3-block first-argmax, zero rest.
//
// R15 = R12 structure (TMA bulk-async staging + vectorized 3x12-patch
// compute, load=evict_last / store=evict_first — the proven-best policy
// combo) with tile doubled to 12 rows (72KB dynamic smem, 512 threads,
// grid 2048). Halves the per-byte fixed costs: mbarrier setup, policy
// creation, fences, commit/wait, syncthreads, CTA launch/retire and the
// end-of-CTA store-drain tail.

static constexpr int W  = 1536;
static constexpr int H  = 1536;
static constexpr int BC = 16;                    // batch * channels
static constexpr int TROWS = 12;                 // rows per tile
static constexpr int TILE_FLOATS = TROWS * W;    // 18432 floats
static constexpr int TILE_BYTES  = TILE_FLOATS * 4;   // 73728
static constexpr int NTHREADS = 512;             // 1 thread = one 3x12 patch
static constexpr int NPATCH = (TROWS / 3) * (W / 12); // 512
static constexpr int TILES_PER_IMAGE = H / TROWS;     // 128
static constexpr int NTILES = BC * TILES_PER_IMAGE;   // 2048
static constexpr int SMEM_TOTAL = TILE_BYTES + 8;     // tile + mbarrier

__global__ __launch_bounds__(NTHREADS)
void pooling_nms_kernel(const float* __restrict__ x, float* __restrict__ out) {
    extern __shared__ __align__(128) char smem[];
    float* tile = reinterpret_cast<float*>(smem);

    const int tid = threadIdx.x;
    const int b   = blockIdx.x;
    const size_t base = (size_t)b * TILE_FLOATS;   // tiles contiguous in gmem

    uint32_t s_tile;
    asm("{ .reg .u64 t; cvta.to.shared.u64 t, %1; cvt.u32.u64 %0, t; }"
        : "=r"(s_tile) : "l"(smem));
    const uint32_t s_mbar = s_tile + TILE_BYTES;

    // Stage 1: one bulk-async load of the whole 72KB tile.
    if (tid == 0) {
        asm volatile("mbarrier.init.shared.b64 [%0], 1;" :: "r"(s_mbar) : "memory");
        asm volatile("mbarrier.arrive.expect_tx.shared.b64 _, [%0], %1;"
                     :: "r"(s_mbar), "r"((uint32_t)TILE_BYTES) : "memory");
        asm volatile(
            "{\n\t"
            ".reg .b64 pol;\n\t"
            "createpolicy.fractional.L2::evict_last.b64 pol, 1.0;\n\t"
            "cp.async.bulk.shared::cta.global.mbarrier::complete_tx::bytes.L2::cache_hint"
            " [%0], [%1], %2, [%3], pol;\n\t"
            "}"
            :: "r"(s_tile), "l"(x + base), "r"((uint32_t)TILE_BYTES),
               "r"(s_mbar)
            : "memory");
    }
    __syncthreads();   // mbarrier.init visible to all waiters

    // All threads wait on the mbarrier (phase 0).
    {
        uint32_t done;
        asm volatile(
            "{\n\t"
            ".reg .pred p;\n\t"
            "mbarrier.try_wait.parity.acquire.cta.shared::cta.b64 p, [%1], 0;\n\t"
            "selp.b32 %0, 1, 0, p;\n\t"
            "}"
            : "=r"(done) : "r"(s_mbar) : "memory");
        if (!done) {
            asm volatile(
                "{\n\t"
                ".reg .pred P1;\n\t"
                "WL_%=:\n\t"
                "mbarrier.try_wait.parity.acquire.cta.shared::cta.b64 P1, [%0], 0, 0x989680;\n\t"
                "@P1 bra.uni WD_%=;\n\t"
                "bra.uni WL_%=;\n\t"
                "WD_%=:\n\t"
                "}"
                :: "r"(s_mbar) : "memory");
        }
    }

    // Stage 2: thread owns one 3x12 patch (4 pool blocks).
    // 9 LDS.128 -> running argmax -> register reconstruct -> 9 STS.128.
    {
        const int g  = tid >> 7;            // row-group within tile (0..3)
        const int pw = tid & 127;           // patch column (0..127)
        float* rp = tile + g * 3 * W + pw * 12;

        float best[4];
        int   bofs[4];                      // code = dr*12 + col

        float v[3][12];
        #pragma unroll
        for (int dr = 0; dr < 3; dr++) {
            float4 a = *reinterpret_cast<const float4*>(rp + dr * W);
            float4 q = *reinterpret_cast<const float4*>(rp + dr * W + 4);
            float4 c = *reinterpret_cast<const float4*>(rp + dr * W + 8);
            v[dr][0]=a.x; v[dr][1]=a.y; v[dr][2]=a.z;  v[dr][3]=a.w;
            v[dr][4]=q.x; v[dr][5]=q.y; v[dr][6]=q.z;  v[dr][7]=q.w;
            v[dr][8]=c.x; v[dr][9]=c.y; v[dr][10]=c.z; v[dr][11]=c.w;
            #pragma unroll
            for (int col = 0; col < 12; col++) {
                const int blk  = col / 3;
                const int code = dr * 12 + col;
                if (dr == 0 && (col % 3) == 0) {
                    best[blk] = v[dr][col]; bofs[blk] = code;
                } else if (v[dr][col] > best[blk]) {   // strict >: first max
                    best[blk] = v[dr][col]; bofs[blk] = code;
                }
            }
        }

        #pragma unroll
        for (int dr = 0; dr < 3; dr++) {
            float t[12];
            #pragma unroll
            for (int col = 0; col < 12; col++) {
                const int blk  = col / 3;
                const int code = dr * 12 + col;
                t[col] = (bofs[blk] == code) ? best[blk] : 0.0f;
            }
            *reinterpret_cast<float4*>(rp + dr * W)     = make_float4(t[0], t[1], t[2], t[3]);
            *reinterpret_cast<float4*>(rp + dr * W + 4) = make_float4(t[4], t[5], t[6], t[7]);
            *reinterpret_cast<float4*>(rp + dr * W + 8) = make_float4(t[8], t[9], t[10], t[11]);
        }
    }
    __syncthreads();   // all STS complete before async-proxy store reads smem

    // Stage 3: one bulk-async store of the whole tile (evict_first policy).
    if (tid == 0) {
        asm volatile("fence.proxy.async.shared::cta;" ::: "memory");
        asm volatile(
            "{\n\t"
            ".reg .b64 pol;\n\t"
            "createpolicy.fractional.L2::evict_first.b64 pol, 1.0;\n\t"
            "cp.async.bulk.global.shared::cta.bulk_group.L2::cache_hint"
            " [%0], [%1], %2, pol;\n\t"
            "}"
            :: "l"(out + base), "r"(s_tile), "r"((uint32_t)TILE_BYTES)
            : "memory");
        asm volatile("cp.async.bulk.commit_group;" ::: "memory");
        // smem must stay valid until the bulk store has read it.
        asm volatile("cp.async.bulk.wait_group.read 0;" ::: "memory");
    }
}

extern "C" void kernel_launch(void* const* d_in, const int* in_sizes, int n_in,
                              void* d_out, int out_size) {
    const float* x = (const float*)d_in[0];
    float* out = (float*)d_out;
    cudaFuncSetAttribute(pooling_nms_kernel,
                         cudaFuncAttributeMaxDynamicSharedMemorySize, SMEM_TOTAL);
    pooling_nms_kernel<<<NTILES, NTHREADS, SMEM_TOTAL>>>(x, out);
}

// round 16
// speedup vs baseline: 1.0213x; 1.0213x over previous
#include <cuda_runtime.h>
#include <cstdint>

// PoolingNms: MaxPool2d(k=3, stride=3) + MaxUnpool2d fused.
// x: [16, 1, 1536, 1536] fp32. Keep per-3x3-block first-argmax, zero rest.
//
// R16 = R12 (best: 36KB TMA-staged tiles, 4096 CTAs, vectorized 3x12-patch
// compute, load=evict_last / store=evict_first) + intra-CTA split-half
// pipeline: the tile is loaded as two 18KB bulk copies with separate
// mbarriers (each row-group's threads wait only for their half), and the
// half-0 bulk store is committed right after half-0 compute (warps 0-3
// bar.sync), overlapping with half-1 compute.

static constexpr int W  = 1536;
static constexpr int H  = 1536;
static constexpr int BC = 16;                    // batch * channels
static constexpr int TROWS = 6;                  // rows per tile
static constexpr int TILE_FLOATS = TROWS * W;    // 9216 floats
static constexpr int HALF_FLOATS = TILE_FLOATS / 2;   // 4608 (3 rows)
static constexpr int HALF_BYTES  = HALF_FLOATS * 4;   // 18432
static constexpr int NTHREADS = 256;
static constexpr int TILES_PER_IMAGE = H / TROWS;            // 256
static constexpr int NTILES = BC * TILES_PER_IMAGE;          // 4096

__global__ __launch_bounds__(NTHREADS)
void pooling_nms_kernel(const float* __restrict__ x, float* __restrict__ out) {
    __shared__ __align__(128) float tile[TILE_FLOATS];
    __shared__ __align__(8) uint64_t mbar[2];

    const int tid = threadIdx.x;
    const int b   = blockIdx.x;
    const size_t base = (size_t)b * TILE_FLOATS;   // tiles contiguous in gmem

    uint32_t s_tile, s_mbar0;
    asm("{ .reg .u64 t; cvta.to.shared.u64 t, %1; cvt.u32.u64 %0, t; }"
        : "=r"(s_tile) : "l"(tile));
    asm("{ .reg .u64 t; cvta.to.shared.u64 t, %1; cvt.u32.u64 %0, t; }"
        : "=r"(s_mbar0) : "l"(&mbar[0]));

    // Stage 1: two 18KB bulk-async loads, one mbarrier per half.
    if (tid == 0) {
        #pragma unroll
        for (int hh = 0; hh < 2; hh++) {
            const uint32_t mb = s_mbar0 + hh * 8;
            asm volatile("mbarrier.init.shared.b64 [%0], 1;" :: "r"(mb) : "memory");
            asm volatile("mbarrier.arrive.expect_tx.shared.b64 _, [%0], %1;"
                         :: "r"(mb), "r"((uint32_t)HALF_BYTES) : "memory");
            asm volatile(
                "{\n\t.reg .b64 pol;\n\t"
                "createpolicy.fractional.L2::evict_last.b64 pol, 1.0;\n\t"
                "cp.async.bulk.shared::cta.global.mbarrier::complete_tx::bytes.L2::cache_hint"
                " [%0], [%1], %2, [%3], pol;\n\t}"
                :: "r"(s_tile + hh * HALF_BYTES),
                   "l"(x + base + hh * HALF_FLOATS),
                   "r"((uint32_t)HALF_BYTES), "r"(mb)
                : "memory");
        }
    }
    __syncthreads();   // mbarrier.init visible to all waiters

    const int g  = tid >> 7;            // row-group / half (0..1)
    const int pw = tid & 127;           // patch column (0..127)

    // Wait only on this half's mbarrier (phase 0).
    {
        const uint32_t mb = s_mbar0 + g * 8;
        uint32_t done;
        asm volatile(
            "{\n\t.reg .pred p;\n\t"
            "mbarrier.try_wait.parity.acquire.cta.shared::cta.b64 p, [%1], 0;\n\t"
            "selp.b32 %0, 1, 0, p;\n\t}"
            : "=r"(done) : "r"(mb) : "memory");
        if (!done) {
            asm volatile(
                "{\n\t.reg .pred P1;\n\t"
                "WL_%=:\n\t"
                "mbarrier.try_wait.parity.acquire.cta.shared::cta.b64 P1, [%0], 0, 0x989680;\n\t"
                "@P1 bra.uni WD_%=;\n\t"
                "bra.uni WL_%=;\n\t"
                "WD_%=:\n\t}"
                :: "r"(mb) : "memory");
        }
    }

    // Stage 2: thread owns one 3x12 patch (4 pool blocks) of its half.
    {
        float* rp = tile + g * HALF_FLOATS + pw * 12;

        float best[4];
        int   bofs[4];                      // code = dr*12 + col
        float v[3][12];
        #pragma unroll
        for (int dr = 0; dr < 3; dr++) {
            float4 a = *reinterpret_cast<const float4*>(rp + dr * W);
            float4 q = *reinterpret_cast<const float4*>(rp + dr * W + 4);
            float4 c = *reinterpret_cast<const float4*>(rp + dr * W + 8);
            v[dr][0]=a.x; v[dr][1]=a.y; v[dr][2]=a.z;  v[dr][3]=a.w;
            v[dr][4]=q.x; v[dr][5]=q.y; v[dr][6]=q.z;  v[dr][7]=q.w;
            v[dr][8]=c.x; v[dr][9]=c.y; v[dr][10]=c.z; v[dr][11]=c.w;
            #pragma unroll
            for (int col = 0; col < 12; col++) {
                const int blk  = col / 3;
                const int code = dr * 12 + col;
                if (dr == 0 && (col % 3) == 0) {
                    best[blk] = v[dr][col]; bofs[blk] = code;
                } else if (v[dr][col] > best[blk]) {   // strict >: first max
                    best[blk] = v[dr][col]; bofs[blk] = code;
                }
            }
        }
        #pragma unroll
        for (int dr = 0; dr < 3; dr++) {
            float t[12];
            #pragma unroll
            for (int col = 0; col < 12; col++) {
                const int blk  = col / 3;
                const int code = dr * 12 + col;
                t[col] = (bofs[blk] == code) ? best[blk] : 0.0f;
            }
            *reinterpret_cast<float4*>(rp + dr * W)     = make_float4(t[0], t[1], t[2], t[3]);
            *reinterpret_cast<float4*>(rp + dr * W + 4) = make_float4(t[4], t[5], t[6], t[7]);
            *reinterpret_cast<float4*>(rp + dr * W + 8) = make_float4(t[8], t[9], t[10], t[11]);
        }
    }

    // Half-0 store: warps 0-3 sync among themselves, then tid0 commits the
    // half-0 bulk store while half-1 threads are still computing.
    if (g == 0) {
        asm volatile("bar.sync 1, 128;" ::: "memory");
        if (tid == 0) {
            asm volatile("fence.proxy.async.shared::cta;" ::: "memory");
            asm volatile(
                "{\n\t.reg .b64 pol;\n\t"
                "createpolicy.fractional.L2::evict_first.b64 pol, 1.0;\n\t"
                "cp.async.bulk.global.shared::cta.bulk_group.L2::cache_hint"
                " [%0], [%1], %2, pol;\n\t}"
                :: "l"(out + base), "r"(s_tile), "r"((uint32_t)HALF_BYTES)
                : "memory");
            asm volatile("cp.async.bulk.commit_group;" ::: "memory");
        }
    }
    __syncthreads();   // half-1 STS complete before its async-proxy store

    // Half-1 store + drain.
    if (tid == 0) {
        asm volatile("fence.proxy.async.shared::cta;" ::: "memory");
        asm volatile(
            "{\n\t.reg .b64 pol;\n\t"
            "createpolicy.fractional.L2::evict_first.b64 pol, 1.0;\n\t"
            "cp.async.bulk.global.shared::cta.bulk_group.L2::cache_hint"
            " [%0], [%1], %2, pol;\n\t}"
            :: "l"(out + base + HALF_FLOATS),
               "r"(s_tile + HALF_BYTES), "r"((uint32_t)HALF_BYTES)
            : "memory");
        asm volatile("cp.async.bulk.commit_group;" ::: "memory");
        // smem must stay valid until both bulk stores have read it.
        asm volatile("cp.async.bulk.wait_group.read 0;" ::: "memory");
    }
}

extern "C" void kernel_launch(void* const* d_in, const int* in_sizes, int n_in,
                              void* d_out, int out_size) {
    const float* x = (const float*)d_in[0];
    float* out = (float*)d_out;
    pooling_nms_kernel<<<NTILES, NTHREADS>>>(x, out);
}